// round 7
// baseline (speedup 1.0000x reference)
#include <cuda_runtime.h>

// CapsuleLayer dynamic routing, multi-kernel factored form v2.
// X[B=128, I=1152, J=128], W[J=128, K=32, D=32], out V[B=128, K=32, D=32]
//
//  k_pre: Wkjd[k][j][d] = W[j][k][d] ; Wkdj[k][d][j] = W[j][k][d]
//  k0   : colsum partials over i (it0 uniform-c GEMM1)
//  k1   : per (kq,b): y-reduce -> s -> squash -> T (mode 0/1) or out (mode 2)
//  k2   : per (split,b), 3 chunks of 64 i:
//           GEMM2 bl[k,i] (+)= sum_j x[i,j] T[k,j]  (full bl per warp, no partials)
//           in-place softmax_k ; GEMM1 y_partial[k,j] += sum_i c[i,k] x[i,j]

#define BB 128
#define II 1152
#define JJ 128
#define KK 32
#define DD 32
#define KD 1024
#define NSPLIT 6
#define ILEN 192         // II / NSPLIT
#define CI 64
#define NCH 3            // ILEN / CI
#define XPF 132
#define NYP (NSPLIT*2)   // 12 y-partial slots (i-half per CTA)

typedef unsigned long long u64;

#define FMA2(d,a,b,c) asm("fma.rn.f32x2 %0, %1, %2, %3;" : "=l"(d) : "l"(a), "l"(b), "l"(c))
#define ADD2(d,a,b)   asm("add.rn.f32x2 %0, %1, %2;" : "=l"(d) : "l"(a), "l"(b))
#define PACK2(d,s)    asm("mov.b64 %0, {%1, %1};" : "=l"(d) : "r"(__float_as_uint(s)))

__device__ float g_bl[(size_t)BB * KK * II];          // [b][k][i]
__device__ float g_T[(size_t)BB * KK * JJ];           // [b][k][j]
__device__ float g_yp[(size_t)BB * NYP * KK * JJ];    // [b][slot][k][j]
__device__ float g_ycol[(size_t)BB * 4 * JJ];         // [b][p][j]
__device__ float g_Wkjd[(size_t)KK * JJ * DD];        // [k][j][d]
__device__ float g_Wkdj[(size_t)KK * DD * JJ];        // [k][d][j]

// ===================== k_pre: W transposes =====================
__global__ __launch_bounds__(256)
void k_pre(const float* __restrict__ W)
{
    __shared__ float tile[JJ * 33];
    const int k = blockIdx.x, t = threadIdx.x;
    // load W[j][k][d] for this k: thread (j, d)
    #pragma unroll
    for (int ee = 0; ee < 16; ++ee) {
        const int idx = t + ee * 256;          // 4096
        const int j = idx >> 5, d = idx & 31;
        const float v = W[(size_t)j * KD + k * DD + d];   // coalesced over d
        tile[j * 33 + d] = v;
        g_Wkjd[(size_t)k * 4096 + j * 32 + d] = v;        // coalesced
    }
    __syncthreads();
    #pragma unroll
    for (int ee = 0; ee < 16; ++ee) {
        const int idx = t + ee * 256;
        const int d = idx >> 7, j = idx & 127;
        g_Wkdj[(size_t)k * 4096 + d * 128 + j] = tile[j * 33 + d];  // coalesced
    }
}

// ===================== k0: colsum partials =====================
__global__ __launch_bounds__(256)
void k0_colsum(const float* __restrict__ X)
{
    __shared__ ulonglong2 sred[256];
    const int b = blockIdx.y, p = blockIdx.x;
    const int t = threadIdx.x, j4 = t & 31, ih = t >> 5;
    const float* xp = X + (size_t)b * (II * JJ) + (size_t)(p * 288 + ih * 36) * JJ + j4 * 4;
    u64 s0 = 0, s1 = 0;
    #pragma unroll 4
    for (int ii = 0; ii < 36; ++ii) {
        ulonglong2 v = *(const ulonglong2*)(xp + (size_t)ii * JJ);
        ADD2(s0, s0, v.x); ADD2(s1, s1, v.y);
    }
    sred[ih * 32 + j4] = make_ulonglong2(s0, s1);
    __syncthreads();
    if (t < 32) {
        u64 a0 = 0, a1 = 0;
        #pragma unroll
        for (int h = 0; h < 8; ++h) {
            ulonglong2 v = sred[h * 32 + t];
            ADD2(a0, a0, v.x); ADD2(a1, a1, v.y);
        }
        ((ulonglong2*)(g_ycol + (size_t)(b * 4 + p) * JJ))[t] = make_ulonglong2(a0, a1);
    }
}

// ===================== k1: y -> s -> v -> T / out =====================
__global__ __launch_bounds__(256)
void k1_svt(float* __restrict__ out, int mode)
{
    __shared__ float ym[8 * JJ];
    __shared__ float sv[8 * DD];

    const int b = blockIdx.y, kq = blockIdx.x;
    const int t = threadIdx.x, lane = t & 31, kl = t >> 5;   // 8 warps, warp=one k
    const int k = kq * 8 + kl;

    if (mode == 0) {
        const float* yc = g_ycol + (size_t)b * 4 * JJ;
        #pragma unroll
        for (int pp = 0; pp < 4; ++pp) {
            const int idx = t + pp * 256;                    // 1024
            const int j = idx & 127;
            ym[idx] = (yc[j] + yc[128 + j] + yc[256 + j] + yc[384 + j]) * (1.0f / 32.0f);
        }
    } else {
        const float* yp = g_yp + (size_t)b * NYP * KK * JJ;
        #pragma unroll
        for (int pp = 0; pp < 4; ++pp) {
            const int idx = t + pp * 256;
            const int kl2 = idx >> 7, j = idx & 127;
            const size_t off = (size_t)(kq * 8 + kl2) * JJ + j;
            float acc = 0.f;
            #pragma unroll
            for (int s = 0; s < NYP; ++s)
                acc += yp[(size_t)s * KK * JJ + off];
            ym[idx] = acc;
        }
    }
    __syncthreads();

    // s[k][d]: thread (kl, d=lane), coalesced Wkjd rows
    float sacc = 0.f;
    {
        const float* Wp = g_Wkjd + (size_t)k * 4096 + lane;
        const float* yk = ym + kl * JJ;
        #pragma unroll 16
        for (int j = 0; j < JJ; ++j)
            sacc = fmaf(yk[j], Wp[j * 32], sacc);
    }
    // squash via warp reduce
    float ss = sacc * sacc;
    #pragma unroll
    for (int off = 16; off > 0; off >>= 1)
        ss += __shfl_xor_sync(0xffffffffu, ss, off);
    const float scale = ss / (1.0f + ss) * rsqrtf(ss + 1e-7f);
    const float v = sacc * scale;

    if (mode == 2) {
        out[(size_t)b * KK * DD + k * DD + lane] = v;
        return;
    }

    sv[kl * DD + lane] = v;
    __syncwarp();

    // T[k][j]: warp kl, j = lane + 32q, coalesced Wkdj rows
    float* Tg = g_T + (size_t)b * KK * JJ + k * JJ;
    float ta[4] = {0.f, 0.f, 0.f, 0.f};
    const float* Wd = g_Wkdj + (size_t)k * 4096 + lane;
    #pragma unroll 8
    for (int d = 0; d < DD; ++d) {
        const float vd = sv[kl * DD + d];
        const float* r = Wd + d * 128;
        #pragma unroll
        for (int q = 0; q < 4; ++q)
            ta[q] = fmaf(vd, r[32 * q], ta[q]);
    }
    #pragma unroll
    for (int q = 0; q < 4; ++q)
        Tg[lane + 32 * q] = ta[q];
}

// ===================== k2: streaming GEMM2 -> softmax -> GEMM1 =====================
#define K2_XS 0          // 64*132 = 8448
#define K2_TM 8448       // 4096
#define K2_BL 12544      // 64*36 = 2304  (bl chunk, softmax in place)
#define K2_FLOATS 14848
#define K2_SMEM (K2_FLOATS * 4)

__global__ __launch_bounds__(256, 3)
void k2_stream(const float* __restrict__ X, int trans)
{
    extern __shared__ float sm[];
    float* xs  = sm + K2_XS;
    float* Tm  = sm + K2_TM;
    float* blc = sm + K2_BL;

    const int b = blockIdx.y, split = blockIdx.x;
    const int t = threadIdx.x, lane = t & 31, w = t >> 5;   // 8 warps
    const int kg = w & 3, ih = w >> 2;                      // 8 k's, i-half
    const int ibase0 = split * ILEN;

    const float* __restrict__ xg = X + (size_t)b * (II * JJ);
    float* __restrict__ blg = g_bl + (size_t)b * (KK * II);

    // load T tile (4096 f)
    {
        const float4* Tg = (const float4*)(g_T + (size_t)b * KK * JJ);
        #pragma unroll
        for (int ee = 0; ee < 4; ++ee)
            ((float4*)Tm)[t + ee * 256] = Tg[t + ee * 256];
    }

    u64 a1[8][2];
    #pragma unroll
    for (int q = 0; q < 8; ++q) { a1[q][0] = 0; a1[q][1] = 0; }

    for (int ch = 0; ch < NCH; ++ch) {
        const int ibase = ibase0 + ch * CI;
        __syncthreads();                      // xs free (also orders Tm on ch0)
        // stage 64x128 f (8 float4 per thread, coalesced)
        #pragma unroll
        for (int ee = 0; ee < 8; ++ee) {
            const int e4 = t + ee * 256;
            const int il = e4 >> 5, j4 = e4 & 31;
            *(float4*)(xs + il * XPF + j4 * 4) =
                *(const float4*)(xg + (size_t)(ibase + il) * JJ + j4 * 4);
        }
        // prefetch old bl for += (independent of smem)
        float blold[8];
        if (trans) {
            #pragma unroll
            for (int q = 0; q < 8; ++q)
                blold[q] = blg[(size_t)(kg * 8 + q) * II + ibase + ih * 32 + lane];
        }
        __syncthreads();

        // ---- GEMM2: warp = 8 k x 32 i (lane, half ih) x full 128 j ----
        {
            u64 a2[8];
            #pragma unroll
            for (int q = 0; q < 8; ++q) a2[q] = 0;
            const float* xr = xs + (ih * 32 + lane) * XPF;
            #pragma unroll 4
            for (int jq = 0; jq < 32; ++jq) {
                ulonglong2 xv = *(const ulonglong2*)(xr + jq * 4);
                #pragma unroll
                for (int q = 0; q < 8; ++q) {
                    ulonglong2 tq = *(const ulonglong2*)(Tm + (kg * 8 + q) * JJ + jq * 4);
                    FMA2(a2[q], tq.x, xv.x, a2[q]);
                    FMA2(a2[q], tq.y, xv.y, a2[q]);
                }
            }
            #pragma unroll
            for (int q = 0; q < 8; ++q) {
                float2 f = *(float2*)&a2[q];
                float val = f.x + f.y;
                if (trans) val += blold[q];
                blg[(size_t)(kg * 8 + q) * II + ibase + ih * 32 + lane] = val;
                blc[(ih * 32 + lane) * 36 + kg * 8 + q] = val;
            }
        }
        __syncthreads();

        // ---- softmax over k, in place (4 threads per i, 8 k each) ----
        {
            const int i = t >> 2, kq8 = (t & 3) * 8;
            float* r = blc + i * 36 + kq8;
            float4 u0 = *(const float4*)(r);
            float4 u1 = *(const float4*)(r + 4);
            float mx = fmaxf(fmaxf(fmaxf(u0.x, u0.y), fmaxf(u0.z, u0.w)),
                             fmaxf(fmaxf(u1.x, u1.y), fmaxf(u1.z, u1.w)));
            mx = fmaxf(mx, __shfl_xor_sync(0xffffffffu, mx, 1));
            mx = fmaxf(mx, __shfl_xor_sync(0xffffffffu, mx, 2));
            u0.x = __expf(u0.x - mx); u0.y = __expf(u0.y - mx);
            u0.z = __expf(u0.z - mx); u0.w = __expf(u0.w - mx);
            u1.x = __expf(u1.x - mx); u1.y = __expf(u1.y - mx);
            u1.z = __expf(u1.z - mx); u1.w = __expf(u1.w - mx);
            float ssum = u0.x + u0.y + u0.z + u0.w + u1.x + u1.y + u1.z + u1.w;
            ssum += __shfl_xor_sync(0xffffffffu, ssum, 1);
            ssum += __shfl_xor_sync(0xffffffffu, ssum, 2);
            const float inv = 1.0f / ssum;
            u0.x *= inv; u0.y *= inv; u0.z *= inv; u0.w *= inv;
            u1.x *= inv; u1.y *= inv; u1.z *= inv; u1.w *= inv;
            *(float4*)(r) = u0;
            *(float4*)(r + 4) = u1;
        }
        __syncthreads();

        // ---- GEMM1: warp = 8 k x 32 i (half ih) x full 128 j (lane*4) ----
        #pragma unroll 2
        for (int ii = 0; ii < 32; ++ii) {
            const int i = ih * 32 + ii;
            ulonglong2 xv = *(const ulonglong2*)(xs + i * XPF + lane * 4);
            const float* cr = blc + i * 36 + kg * 8;         // broadcast
            float4 c0 = *(const float4*)(cr);
            float4 c1 = *(const float4*)(cr + 4);
            u64 cc;
            PACK2(cc, c0.x); FMA2(a1[0][0], cc, xv.x, a1[0][0]); FMA2(a1[0][1], cc, xv.y, a1[0][1]);
            PACK2(cc, c0.y); FMA2(a1[1][0], cc, xv.x, a1[1][0]); FMA2(a1[1][1], cc, xv.y, a1[1][1]);
            PACK2(cc, c0.z); FMA2(a1[2][0], cc, xv.x, a1[2][0]); FMA2(a1[2][1], cc, xv.y, a1[2][1]);
            PACK2(cc, c0.w); FMA2(a1[3][0], cc, xv.x, a1[3][0]); FMA2(a1[3][1], cc, xv.y, a1[3][1]);
            PACK2(cc, c1.x); FMA2(a1[4][0], cc, xv.x, a1[4][0]); FMA2(a1[4][1], cc, xv.y, a1[4][1]);
            PACK2(cc, c1.y); FMA2(a1[5][0], cc, xv.x, a1[5][0]); FMA2(a1[5][1], cc, xv.y, a1[5][1]);
            PACK2(cc, c1.z); FMA2(a1[6][0], cc, xv.x, a1[6][0]); FMA2(a1[6][1], cc, xv.y, a1[6][1]);
            PACK2(cc, c1.w); FMA2(a1[7][0], cc, xv.x, a1[7][0]); FMA2(a1[7][1], cc, xv.y, a1[7][1]);
        }
    }

    // y partial slot = (split, ih): warp kg owns k = kg*8..kg*8+7
    float* yp = g_yp + ((size_t)(b * NSPLIT + split) * 2 + ih) * KK * JJ;
    #pragma unroll
    for (int q = 0; q < 8; ++q)
        *(ulonglong2*)(yp + (kg * 8 + q) * JJ + lane * 4) =
            make_ulonglong2(a1[q][0], a1[q][1]);
}

extern "C" void kernel_launch(void* const* d_in, const int* in_sizes, int n_in,
                              void* d_out, int out_size)
{
    (void)in_sizes; (void)n_in; (void)out_size;
    const float* X = (const float*)d_in[0];   // [128, 1152, 128] f32
    const float* W = (const float*)d_in[1];   // [128, 32, 32] f32
    float* out = (float*)d_out;               // [128, 32, 32] f32

    cudaFuncSetAttribute(k2_stream, cudaFuncAttributeMaxDynamicSharedMemorySize, K2_SMEM);

    k_pre<<<KK, 256>>>(W);
    k0_colsum<<<dim3(4, BB), 256>>>(X);
    k1_svt<<<dim3(4, BB), 256>>>(out, 0);
    k2_stream<<<dim3(NSPLIT, BB), 256, K2_SMEM>>>(X, 0);
    k1_svt<<<dim3(4, BB), 256>>>(out, 1);
    k2_stream<<<dim3(NSPLIT, BB), 256, K2_SMEM>>>(X, 1);
    k1_svt<<<dim3(4, BB), 256>>>(out, 2);
}

// round 8
// speedup vs baseline: 1.0603x; 1.0603x over previous
#include <cuda_runtime.h>

// CapsuleLayer dynamic routing, multi-kernel factored form v3.
// X[B=128, I=1152, J=128], W[J=128, K=32, D=32], out V[B=128, K=32, D=32]
//  k_setup: Wkjd transpose + it0 colsum partials
//  k1     : per (kq, 4 batches): y -> s -> squash -> T / out, W rows reused x4
//  k2     : per (split, b): 6 chunks x 64 i, TWO independent 128-thread groups
//           (named barriers): GEMM2 -> reg-softmax -> GEMM1

#define BB 128
#define II 1152
#define JJ 128
#define KK 32
#define DD 32
#define KD 1024
#define NSPLIT 3
#define ILEN 384
#define CI 64
#define NCH 6
#define C2P 36
#define NYP (NSPLIT*2)

typedef unsigned long long u64;

#define FMA2(d,a,b,c) asm("fma.rn.f32x2 %0, %1, %2, %3;" : "=l"(d) : "l"(a), "l"(b), "l"(c))
#define ADD2(d,a,b)   asm("add.rn.f32x2 %0, %1, %2;" : "=l"(d) : "l"(a), "l"(b))
#define PACK2(d,s)    asm("mov.b64 %0, {%1, %1};" : "=l"(d) : "r"(__float_as_uint(s)))
#define GBAR(id)      asm volatile("bar.sync %0, 128;" :: "r"(id) : "memory")

__device__ float g_bl[(size_t)BB * KK * II];            // [b][k][i]
__device__ float g_T[(size_t)BB * KK * JJ];             // [b][k][j]
__device__ float g_yp[(size_t)BB * NYP * KK * JJ];      // [b][slot][k][j]
__device__ float g_ycol[(size_t)BB * 4 * JJ];           // [b][p][j]
__device__ float g_Wkjd[(size_t)KK * JJ * DD];          // [k][j][d]

// ===================== k_setup: W transpose + it0 colsum =====================
__global__ __launch_bounds__(256)
void k_setup(const float* __restrict__ W, const float* __restrict__ X)
{
    const int t = threadIdx.x;
    if (blockIdx.x < 32) {
        const int k = blockIdx.x;
        #pragma unroll
        for (int ee = 0; ee < 16; ++ee) {
            const int idx = t + ee * 256;            // j*32 + d
            const int j = idx >> 5, d = idx & 31;
            g_Wkjd[(size_t)k * 4096 + idx] = W[(size_t)j * KD + k * DD + d];
        }
        return;
    }
    __shared__ ulonglong2 sred[256];
    const int bid = blockIdx.x - 32;
    const int b = bid & 127, p = bid >> 7;
    const int j4 = t & 31, ih = t >> 5;
    const float* xp = X + (size_t)b * (II * JJ) + (size_t)(p * 288 + ih * 36) * JJ + j4 * 4;
    u64 s0 = 0, s1 = 0;
    #pragma unroll 4
    for (int ii = 0; ii < 36; ++ii) {
        ulonglong2 v = *(const ulonglong2*)(xp + (size_t)ii * JJ);
        ADD2(s0, s0, v.x); ADD2(s1, s1, v.y);
    }
    sred[ih * 32 + j4] = make_ulonglong2(s0, s1);
    __syncthreads();
    if (t < 32) {
        u64 a0 = 0, a1 = 0;
        #pragma unroll
        for (int h = 0; h < 8; ++h) {
            ulonglong2 v = sred[h * 32 + t];
            ADD2(a0, a0, v.x); ADD2(a1, a1, v.y);
        }
        ((ulonglong2*)(g_ycol + (size_t)(b * 4 + p) * JJ))[t] = make_ulonglong2(a0, a1);
    }
}

// ===================== k1: y -> s -> v -> T / out  (4 batches per block) =====================
__global__ __launch_bounds__(256)
void k1_svt(float* __restrict__ out, int mode)
{
    __shared__ float ym[4 * 8 * JJ];    // [bb][kk][j] (mode0: [bb][0][j])
    __shared__ float sv[4 * 8 * DD];

    const int kq = blockIdx.x, bq = blockIdx.y;
    const int t = threadIdx.x, lane = t & 31, w = t >> 5;

    if (mode == 0) {
        #pragma unroll
        for (int ee = 0; ee < 2; ++ee) {
            const int e = t + ee * 256;              // bb*128 + j
            const int bb = e >> 7, j = e & 127;
            const float* yc = g_ycol + (size_t)(bq * 4 + bb) * 4 * JJ;
            ym[bb * 1024 + j] =
                (yc[j] + yc[128 + j] + yc[256 + j] + yc[384 + j]) * (1.0f / 32.0f);
        }
    } else {
        #pragma unroll
        for (int ee = 0; ee < 16; ++ee) {
            const int e = t + ee * 256;              // bb*1024 + kk*128 + j
            const int bb = e >> 10, kk = (e >> 7) & 7, j = e & 127;
            const size_t base = (size_t)(bq * 4 + bb) * NYP * KK * JJ
                              + (size_t)(kq * 8 + kk) * JJ + j;
            float acc = 0.f;
            #pragma unroll
            for (int s = 0; s < NYP; ++s)
                acc += g_yp[base + (size_t)s * KK * JJ];
            ym[e] = acc;
        }
    }
    __syncthreads();

    // s: thread = (kk=w, d=lane); W element reused across 4 batches
    const int kk = w, d = lane;
    const int k = kq * 8 + kk;
    float s[4] = {0.f, 0.f, 0.f, 0.f};
    {
        const float* Wp = g_Wkjd + (size_t)k * 4096 + d;
        const int koff = mode ? kk * 128 : 0;
        #pragma unroll 8
        for (int j = 0; j < JJ; ++j) {
            const float wv = Wp[j * 32];             // coalesced over d
            #pragma unroll
            for (int bb = 0; bb < 4; ++bb)
                s[bb] = fmaf(ym[bb * 1024 + koff + j], wv, s[bb]);
        }
    }
    #pragma unroll
    for (int bb = 0; bb < 4; ++bb) {
        float ss = s[bb] * s[bb];
        #pragma unroll
        for (int off = 16; off > 0; off >>= 1)
            ss += __shfl_xor_sync(0xffffffffu, ss, off);
        const float v = s[bb] * (ss / (1.0f + ss) * rsqrtf(ss + 1e-7f));
        if (mode == 2) out[(size_t)(bq * 4 + bb) * KK * DD + k * DD + d] = v;
        else           sv[(bb * 8 + kk) * DD + d] = v;
    }
    if (mode == 2) return;
    __syncthreads();

    // T[bb][k][j]: warp kk, lane = j%32; W row contiguous (L1-hot from phase B)
    #pragma unroll
    for (int jq = 0; jq < 4; ++jq) {
        const int j = jq * 32 + lane;
        const float4* Wr = (const float4*)(g_Wkjd + (size_t)k * 4096 + j * 32);
        float acc[4] = {0.f, 0.f, 0.f, 0.f};
        #pragma unroll
        for (int d4 = 0; d4 < 8; ++d4) {
            const float4 w4 = Wr[d4];
            #pragma unroll
            for (int bb = 0; bb < 4; ++bb) {
                const float4 s4 = ((const float4*)(sv + (bb * 8 + kk) * DD))[d4];
                acc[bb] += w4.x * s4.x + w4.y * s4.y + w4.z * s4.z + w4.w * s4.w;
            }
        }
        #pragma unroll
        for (int bb = 0; bb < 4; ++bb)
            g_T[(size_t)(bq * 4 + bb) * KK * JJ + k * JJ + j] = acc[bb];
    }
}

// ===================== k2: streaming GEMM2 -> reg softmax -> GEMM1 =====================
#define K2_XS 0          // 64*128 = 8192 f, XOR-swizzled
#define K2_TM 8192       // 4096 f
#define K2_C2 12288      // 64*36: c at [0,32), partial sums at [32,36)
#define K2_FLOATS 14592
#define K2_SMEM (K2_FLOATS * 4)

__global__ __launch_bounds__(256, 3)
void k2_stream(const float* __restrict__ X, int trans)
{
    extern __shared__ float sm[];
    float* xs = sm + K2_XS;
    float* Tm = sm + K2_TM;
    float* c2 = sm + K2_C2;

    const int b = blockIdx.y, split = blockIdx.x;
    const int t = threadIdx.x, lane = t & 31, w = t >> 5;
    const int kg = w & 3, ih = w >> 2;          // group ih = warps {4ih..4ih+3}
    const int gt = t & 127;
    const int barid = 1 + ih;
    const int iL = ih * 32 + lane;

    const float* __restrict__ xg = X + (size_t)b * (II * JJ);
    float* __restrict__ blg = g_bl + (size_t)b * (KK * II);

    {
        const float4* Tg = (const float4*)(g_T + (size_t)b * KK * JJ);
        #pragma unroll
        for (int ee = 0; ee < 4; ++ee)
            ((float4*)Tm)[t + ee * 256] = Tg[t + ee * 256];
    }
    u64 a1[8][2];
    #pragma unroll
    for (int q = 0; q < 8; ++q) { a1[q][0] = 0; a1[q][1] = 0; }
    __syncthreads();                            // Tm visible to both groups

    for (int ch = 0; ch < NCH; ++ch) {
        const int ibase = split * ILEN + ch * CI;

        // stage own group's 32 rows (XOR swizzle on 16B cols)
        #pragma unroll
        for (int ee = 0; ee < 8; ++ee) {
            const int e4 = gt + ee * 128;       // il_loc*32 + j4
            const int il = ih * 32 + (e4 >> 5), j4 = e4 & 31;
            const float4 vv = *(const float4*)(xg + (size_t)(ibase + il) * JJ + j4 * 4);
            *(float4*)(xs + il * 128 + ((j4 ^ (il & 31)) << 2)) = vv;
        }
        float blold[8];
        if (trans) {
            #pragma unroll
            for (int q = 0; q < 8; ++q)
                blold[q] = blg[(size_t)(kg * 8 + q) * II + ibase + iL];
        }
        GBAR(barid);

        // GEMM2: warp = 8 k x 32 i (lane) x 128 j
        u64 a2[8];
        #pragma unroll
        for (int q = 0; q < 8; ++q) a2[q] = 0;
        {
            const float* xr = xs + iL * 128;
            #pragma unroll 4
            for (int jq = 0; jq < 32; ++jq) {
                const ulonglong2 xv = *(const ulonglong2*)(xr + ((jq ^ lane) << 2));
                #pragma unroll
                for (int q = 0; q < 8; ++q) {
                    const ulonglong2 tq = *(const ulonglong2*)(Tm + (kg * 8 + q) * JJ + jq * 4);
                    FMA2(a2[q], tq.x, xv.x, a2[q]);
                    FMA2(a2[q], tq.y, xv.y, a2[q]);
                }
            }
        }
        float ex[8], ssloc = 0.f;
        #pragma unroll
        for (int q = 0; q < 8; ++q) {
            const float2 f = *(float2*)&a2[q];
            float val = f.x + f.y;
            if (trans) val += blold[q];
            blg[(size_t)(kg * 8 + q) * II + ibase + iL] = val;
            ex[q] = __expf(val);                // no max-sub: |bl| small, fp32-safe
            ssloc += ex[q];
        }
        c2[iL * C2P + 32 + kg] = ssloc;
        GBAR(barid);

        // normalize own 8 exps, write c slice
        {
            const float4 sp = *(const float4*)(c2 + iL * C2P + 32);
            const float inv = 1.0f / (sp.x + sp.y + sp.z + sp.w);
            *(float4*)(c2 + iL * C2P + kg * 8) =
                make_float4(ex[0] * inv, ex[1] * inv, ex[2] * inv, ex[3] * inv);
            *(float4*)(c2 + iL * C2P + kg * 8 + 4) =
                make_float4(ex[4] * inv, ex[5] * inv, ex[6] * inv, ex[7] * inv);
        }
        GBAR(barid);

        // GEMM1: warp = 8 k x 32 i (own half) x 128 j (lane*4)
        #pragma unroll 2
        for (int ii = 0; ii < 32; ++ii) {
            const int i = ih * 32 + ii;
            const ulonglong2 xv = *(const ulonglong2*)(xs + i * 128 + ((lane ^ ii) << 2));
            const float4 c0 = *(const float4*)(c2 + i * C2P + kg * 8);   // bcast
            const float4 c1 = *(const float4*)(c2 + i * C2P + kg * 8 + 4);
            u64 cc;
            PACK2(cc, c0.x); FMA2(a1[0][0], cc, xv.x, a1[0][0]); FMA2(a1[0][1], cc, xv.y, a1[0][1]);
            PACK2(cc, c0.y); FMA2(a1[1][0], cc, xv.x, a1[1][0]); FMA2(a1[1][1], cc, xv.y, a1[1][1]);
            PACK2(cc, c0.z); FMA2(a1[2][0], cc, xv.x, a1[2][0]); FMA2(a1[2][1], cc, xv.y, a1[2][1]);
            PACK2(cc, c0.w); FMA2(a1[3][0], cc, xv.x, a1[3][0]); FMA2(a1[3][1], cc, xv.y, a1[3][1]);
            PACK2(cc, c1.x); FMA2(a1[4][0], cc, xv.x, a1[4][0]); FMA2(a1[4][1], cc, xv.y, a1[4][1]);
            PACK2(cc, c1.y); FMA2(a1[5][0], cc, xv.x, a1[5][0]); FMA2(a1[5][1], cc, xv.y, a1[5][1]);
            PACK2(cc, c1.z); FMA2(a1[6][0], cc, xv.x, a1[6][0]); FMA2(a1[6][1], cc, xv.y, a1[6][1]);
            PACK2(cc, c1.w); FMA2(a1[7][0], cc, xv.x, a1[7][0]); FMA2(a1[7][1], cc, xv.y, a1[7][1]);
        }
        GBAR(barid);                            // group's xs/c2 free for next chunk
    }

    // y-partial slot (split, ih)
    float* yp = g_yp + ((size_t)(b * NSPLIT + split) * 2 + ih) * KK * JJ;
    #pragma unroll
    for (int q = 0; q < 8; ++q)
        *(ulonglong2*)(yp + (kg * 8 + q) * JJ + lane * 4) =
            make_ulonglong2(a1[q][0], a1[q][1]);
}

extern "C" void kernel_launch(void* const* d_in, const int* in_sizes, int n_in,
                              void* d_out, int out_size)
{
    (void)in_sizes; (void)n_in; (void)out_size;
    const float* X = (const float*)d_in[0];   // [128, 1152, 128] f32
    const float* W = (const float*)d_in[1];   // [128, 32, 32] f32
    float* out = (float*)d_out;               // [128, 32, 32] f32

    cudaFuncSetAttribute(k2_stream, cudaFuncAttributeMaxDynamicSharedMemorySize, K2_SMEM);

    k_setup<<<32 + 512, 256>>>(W, X);
    k1_svt<<<dim3(4, 32), 256>>>(out, 0);
    k2_stream<<<dim3(NSPLIT, BB), 256, K2_SMEM>>>(X, 0);
    k1_svt<<<dim3(4, 32), 256>>>(out, 1);
    k2_stream<<<dim3(NSPLIT, BB), 256, K2_SMEM>>>(X, 1);
    k1_svt<<<dim3(4, 32), 256>>>(out, 2);
}